// round 5
// baseline (speedup 1.0000x reference)
#include <cuda_runtime.h>
#include <math.h>

#define B_   2
#define S_   4096
#define DM_  1024
#define H_   16
#define HD_  64
#define MROWS (B_ * S_)

__device__ float g_q[MROWS * DM_];
__device__ float g_k[MROWS * DM_];
__device__ float g_v[MROWS * DM_];
__device__ float g_attn[MROWS * DM_];
__device__ float g_xt[MROWS * DM_];
__device__ float g_wqt[DM_ * DM_];
__device__ float g_wkt[DM_ * DM_];
__device__ float g_wvt[DM_ * DM_];
__device__ float g_wot[DM_ * DM_];

__device__ __forceinline__ unsigned f2tf(float x) {
  unsigned r;
  asm("cvt.rna.tf32.f32 %0, %1;" : "=r"(r) : "f"(x));
  return r;
}

__device__ __forceinline__ void mma_tf32(float c[4], const unsigned a[4],
                                         const unsigned b[2]) {
  asm volatile(
      "mma.sync.aligned.m16n8k8.row.col.f32.tf32.tf32.f32 "
      "{%0,%1,%2,%3}, {%4,%5,%6,%7}, {%8,%9}, {%0,%1,%2,%3};"
      : "+f"(c[0]), "+f"(c[1]), "+f"(c[2]), "+f"(c[3])
      : "r"(a[0]), "r"(a[1]), "r"(a[2]), "r"(a[3]), "r"(b[0]), "r"(b[1]));
}

__device__ __forceinline__ void ldsm4(unsigned r[4], const void* p) {
  unsigned a = (unsigned)__cvta_generic_to_shared(p);
  asm volatile(
      "ldmatrix.sync.aligned.m8n8.x4.shared.b16 {%0,%1,%2,%3}, [%4];"
      : "=r"(r[0]), "=r"(r[1]), "=r"(r[2]), "=r"(r[3])
      : "r"(a));
}

__device__ __forceinline__ void cp16(void* smem_dst, const void* gmem_src) {
  unsigned s = (unsigned)__cvta_generic_to_shared(smem_dst);
  asm volatile("cp.async.cg.shared.global [%0], [%1], 16;" ::"r"(s),
               "l"(gmem_src));
}
__device__ __forceinline__ void cp_commit() {
  asm volatile("cp.async.commit_group;");
}
__device__ __forceinline__ void cp_wait1() {
  asm volatile("cp.async.wait_group 1;");
}

// ---------------------------------------------------------------------------
// Pre-pass: tf32 rounding (x) and transpose+round (weights).
// ---------------------------------------------------------------------------
__global__ void tf32_round_kernel(const float* __restrict__ in,
                                  float* __restrict__ out, long n4) {
  long i = (long)blockIdx.x * blockDim.x + threadIdx.x;
  long stride = (long)gridDim.x * blockDim.x;
  for (; i < n4; i += stride) {
    float4 v = ((const float4*)in)[i];
    v.x = __uint_as_float(f2tf(v.x));
    v.y = __uint_as_float(f2tf(v.y));
    v.z = __uint_as_float(f2tf(v.z));
    v.w = __uint_as_float(f2tf(v.w));
    ((float4*)out)[i] = v;
  }
}

// out[n*K+k] = round(in[k*N+n]); square DM_ x DM_.
__global__ __launch_bounds__(256) void tf32_roundT_kernel(
    const float* __restrict__ in, float* __restrict__ out) {
  __shared__ float t[32][33];
  int k0 = blockIdx.x * 32, n0 = blockIdx.y * 32;
  int tx = threadIdx.x & 31, ty = threadIdx.x >> 5;  // ty 0..7
#pragma unroll
  for (int i = 0; i < 32; i += 8)
    t[ty + i][tx] = in[(long)(k0 + ty + i) * DM_ + n0 + tx];
  __syncthreads();
#pragma unroll
  for (int i = 0; i < 32; i += 8)
    out[(long)(n0 + ty + i) * DM_ + k0 + tx] =
        __uint_as_float(f2tf(t[tx][ty + i]));
}

// ---------------------------------------------------------------------------
// GEMM: C = A @ W + bias, W given TRANSPOSED (Wt[n][k]), both tf32-rounded.
// Tile 128x128x32, 3-stage cp.async pipeline (1 sync/iter), LDSM fragments.
// Smem per stage: As 128x36 + Bs 128x36 words. Dynamic: 3*9216*4 = 110592 B.
// ---------------------------------------------------------------------------
#define GSTAGE_W 9216  // words per stage (As 4608 + Bs 4608)

__device__ __forceinline__ void gemm_body(
    const float* __restrict__ A, const float* __restrict__ Wt,
    const float* __restrict__ bias, float* __restrict__ C, int rnd,
    unsigned* gsm, long m0, int n0) {
  const int tid  = threadIdx.x;
  const int lane = tid & 31;
  const int wid  = tid >> 5;
  const int g    = lane >> 2;
  const int tg   = lane & 3;
  const int wm   = wid & 3;
  const int wn   = wid >> 2;

  const int lrow = lane & 7;              // ldsm row-in-octet
  const int lq   = (lane >> 3) & 1;       // ldsm quadrant bits
  const int lc   = (lane >> 4) << 2;

  auto stage = [&](int k0, int buf) {
    unsigned* S = gsm + buf * GSTAGE_W;
#pragma unroll
    for (int i = 0; i < 4; i++) {
      int c = tid + i * 256;
      int r = c >> 3, k4 = (c & 7) << 2;
      cp16(S + r * 36 + k4, A + (m0 + r) * DM_ + k0 + k4);
      cp16(S + 4608 + r * 36 + k4, Wt + (long)(n0 + r) * DM_ + k0 + k4);
    }
    cp_commit();
  };

  float acc[2][8][4];
#pragma unroll
  for (int mt = 0; mt < 2; mt++)
#pragma unroll
    for (int nt = 0; nt < 8; nt++)
#pragma unroll
      for (int j = 0; j < 4; j++) acc[mt][nt][j] = 0.f;

  stage(0, 0);
  stage(32, 1);

  const int NT = DM_ / 32;
  for (int kt = 0; kt < NT; kt++) {
    const int buf = kt % 3;
    cp_wait1();
    __syncthreads();
    if (kt + 2 < NT) stage((kt + 2) * 32, (kt + 2) % 3);
    else cp_commit();

    const unsigned* As = gsm + buf * GSTAGE_W;
    const unsigned* Bs = As + 4608;

#pragma unroll
    for (int ksp = 0; ksp < 2; ksp++) {
      unsigned a[2][2][4];  // [mt][ks-in-pair]
#pragma unroll
      for (int mt = 0; mt < 2; mt++) {
#pragma unroll
        for (int kq = 0; kq < 2; kq++) {
          int row = wm * 32 + mt * 16 + lq * 8 + lrow;
          int col = (2 * ksp + kq) * 8 + lc;
          ldsm4(a[mt][kq], As + row * 36 + col);
        }
      }
#pragma unroll
      for (int nt = 0; nt < 8; nt++) {
        unsigned bb[4];
        int nrow = wn * 64 + nt * 8 + lrow;
        int bcol = ksp * 16 + ((lane >> 3) << 2);
        ldsm4(bb, Bs + nrow * 36 + bcol);
        mma_tf32(acc[0][nt], a[0][0], bb);
        mma_tf32(acc[1][nt], a[1][0], bb);
        mma_tf32(acc[0][nt], a[0][1], bb + 2);
        mma_tf32(acc[1][nt], a[1][1], bb + 2);
      }
    }
  }

#pragma unroll
  for (int mt = 0; mt < 2; mt++) {
    long row = m0 + wm * 32 + mt * 16 + g;
#pragma unroll
    for (int nt = 0; nt < 8; nt++) {
      int col = n0 + wn * 64 + nt * 8 + 2 * tg;
      float2 bb = *(const float2*)(bias + col);
      float v00 = acc[mt][nt][0] + bb.x, v01 = acc[mt][nt][1] + bb.y;
      float v10 = acc[mt][nt][2] + bb.x, v11 = acc[mt][nt][3] + bb.y;
      if (rnd) {
        v00 = __uint_as_float(f2tf(v00));
        v01 = __uint_as_float(f2tf(v01));
        v10 = __uint_as_float(f2tf(v10));
        v11 = __uint_as_float(f2tf(v11));
      }
      *(float2*)(C + row * DM_ + col)       = make_float2(v00, v01);
      *(float2*)(C + (row + 8) * DM_ + col) = make_float2(v10, v11);
    }
  }
}

__global__ __launch_bounds__(256) void gemm_tc_kernel(
    const float* __restrict__ A, const float* __restrict__ Wt,
    const float* __restrict__ bias, float* __restrict__ C, int rnd) {
  extern __shared__ unsigned gsm[];
  gemm_body(A, Wt, bias, C, rnd, gsm, (long)blockIdx.y * 128,
            blockIdx.x * 128);
}

__global__ __launch_bounds__(256) void gemm_qkv_kernel(
    const float* __restrict__ A, const float* __restrict__ Wqt,
    const float* __restrict__ Wkt, const float* __restrict__ Wvt,
    const float* __restrict__ bq, const float* __restrict__ bk,
    const float* __restrict__ bv, float* __restrict__ Qo,
    float* __restrict__ Ko, float* __restrict__ Vo) {
  extern __shared__ unsigned gsm[];
  const float* Wt = (blockIdx.z == 0) ? Wqt : (blockIdx.z == 1) ? Wkt : Wvt;
  const float* bias = (blockIdx.z == 0) ? bq : (blockIdx.z == 1) ? bk : bv;
  float* C = (blockIdx.z == 0) ? Qo : (blockIdx.z == 1) ? Ko : Vo;
  gemm_body(A, Wt, bias, C, 1, gsm, (long)blockIdx.y * 128, blockIdx.x * 128);
}

// ---------------------------------------------------------------------------
// Flash attention, tf32 mma + LDSM. CTA: 128 threads (4 warps), 64 q rows.
// Smem words: Ks 2*64*68, Vs 2*64*72, Ps 64*68 -> 89088 B (2 CTAs/SM).
// ---------------------------------------------------------------------------
__global__ __launch_bounds__(128) void flash_tc_kernel(
    const float* __restrict__ Qg, const float* __restrict__ Kg,
    const float* __restrict__ Vg, float* __restrict__ Og) {
  extern __shared__ unsigned sm[];
  unsigned* Ks = sm;                        // 2 * 4352
  unsigned* Vs = sm + 2 * 4352;             // 2 * 4608
  unsigned* Ps = sm + 2 * 4352 + 2 * 4608;  // 64*68

  const int tid  = threadIdx.x;
  const int lane = tid & 31;
  const int wid  = tid >> 5;
  const int g    = lane >> 2;
  const int tg   = lane & 3;
  const int lrow = lane & 7;
  const int bh   = blockIdx.y;
  const int b    = bh >> 4;
  const int h    = bh & 15;
  const int q0   = blockIdx.x * 64;

  const float* Qb  = Qg + ((long)(b * S_ + q0)) * DM_ + h * HD_;
  const float* Kb0 = Kg + ((long)b * S_) * DM_ + h * HD_;
  const float* Vb0 = Vg + ((long)b * S_) * DM_ + h * HD_;
  float* Ob        = Og + ((long)(b * S_ + q0)) * DM_ + h * HD_;

  const float QSCALE = 0.18033688011112042592f;  // (1/8)*log2(e)

  auto stage = [&](int kb, int p) {
    const float* Kb = Kb0 + (long)(kb * 64) * DM_;
    const float* Vb = Vb0 + (long)(kb * 64) * DM_;
    unsigned* KsD = Ks + p * 4352;
    unsigned* VsD = Vs + p * 4608;
#pragma unroll
    for (int i = 0; i < 8; i++) {
      int idx = tid + i * 128;
      int kv = idx >> 4, d4 = (idx & 15) << 2;
      cp16(KsD + kv * 68 + d4, Kb + (long)kv * DM_ + d4);
      cp16(VsD + kv * 72 + d4, Vb + (long)kv * DM_ + d4);
    }
    cp_commit();
  };

  // Q A-fragments in registers for the whole KV loop
  unsigned qa[8][4];
  {
    int qrow = wid * 16 + g;
#pragma unroll
    for (int ks = 0; ks < 8; ks++) {
      int c = ks * 8 + tg;
      qa[ks][0] = f2tf(QSCALE * Qb[(long)qrow * DM_ + c]);
      qa[ks][1] = f2tf(QSCALE * Qb[(long)(qrow + 8) * DM_ + c]);
      qa[ks][2] = f2tf(QSCALE * Qb[(long)qrow * DM_ + c + 4]);
      qa[ks][3] = f2tf(QSCALE * Qb[(long)(qrow + 8) * DM_ + c + 4]);
    }
  }

  float oacc[8][4];
#pragma unroll
  for (int nt = 0; nt < 8; nt++)
#pragma unroll
    for (int j = 0; j < 4; j++) oacc[nt][j] = 0.f;
  float m0r = -INFINITY, m1r = -INFINITY, l0 = 0.f, l1 = 0.f;

  stage(0, 0);
  stage(1, 1);

  for (int kb = 0; kb < S_ / 64; kb++) {
    const int p = kb & 1;
    cp_wait1();
    __syncthreads();
    const unsigned* KsP = Ks + p * 4352;
    const unsigned* VsP = Vs + p * 4608;

    // ---- S = Q K^T (B-frags via ldmatrix.x4 from Ks[kv][d]) ----
    float sacc[8][4];
#pragma unroll
    for (int nt = 0; nt < 8; nt++)
#pragma unroll
      for (int j = 0; j < 4; j++) sacc[nt][j] = 0.f;
#pragma unroll
    for (int nt = 0; nt < 8; nt++) {
#pragma unroll
      for (int ksp = 0; ksp < 4; ksp++) {
        unsigned kk[4];
        ldsm4(kk, KsP + (nt * 8 + lrow) * 68 + ksp * 16 + ((lane >> 3) << 2));
        mma_tf32(sacc[nt], qa[2 * ksp],     kk);
        mma_tf32(sacc[nt], qa[2 * ksp + 1], kk + 2);
      }
    }

    // ---- online softmax (exp2 domain) ----
    float mx0 = -INFINITY, mx1 = -INFINITY;
#pragma unroll
    for (int nt = 0; nt < 8; nt++) {
      mx0 = fmaxf(mx0, fmaxf(sacc[nt][0], sacc[nt][1]));
      mx1 = fmaxf(mx1, fmaxf(sacc[nt][2], sacc[nt][3]));
    }
#pragma unroll
    for (int off = 1; off <= 2; off <<= 1) {
      mx0 = fmaxf(mx0, __shfl_xor_sync(0xffffffffu, mx0, off));
      mx1 = fmaxf(mx1, __shfl_xor_sync(0xffffffffu, mx1, off));
    }
    float mn0 = fmaxf(m0r, mx0), mn1 = fmaxf(m1r, mx1);
    float al0 = exp2f(m0r - mn0), al1 = exp2f(m1r - mn1);
    m0r = mn0; m1r = mn1;

    float ps0 = 0.f, ps1 = 0.f;
#pragma unroll
    for (int nt = 0; nt < 8; nt++) {
      sacc[nt][0] = exp2f(sacc[nt][0] - mn0);
      sacc[nt][1] = exp2f(sacc[nt][1] - mn0);
      sacc[nt][2] = exp2f(sacc[nt][2] - mn1);
      sacc[nt][3] = exp2f(sacc[nt][3] - mn1);
      ps0 += sacc[nt][0] + sacc[nt][1];
      ps1 += sacc[nt][2] + sacc[nt][3];
    }
#pragma unroll
    for (int off = 1; off <= 2; off <<= 1) {
      ps0 += __shfl_xor_sync(0xffffffffu, ps0, off);
      ps1 += __shfl_xor_sync(0xffffffffu, ps1, off);
    }
    l0 = l0 * al0 + ps0;
    l1 = l1 * al1 + ps1;
#pragma unroll
    for (int nt = 0; nt < 8; nt++) {
      oacc[nt][0] *= al0;
      oacc[nt][1] *= al0;
      oacc[nt][2] *= al1;
      oacc[nt][3] *= al1;
    }

    // ---- store P (tf32) ----
    {
      int pr = wid * 16 + g;
#pragma unroll
      for (int nt = 0; nt < 8; nt++) {
        int col = nt * 8 + 2 * tg;
        Ps[pr * 68 + col]           = f2tf(sacc[nt][0]);
        Ps[pr * 68 + col + 1]       = f2tf(sacc[nt][1]);
        Ps[(pr + 8) * 68 + col]     = f2tf(sacc[nt][2]);
        Ps[(pr + 8) * 68 + col + 1] = f2tf(sacc[nt][3]);
      }
    }
    __syncwarp();

    // ---- O += P V (A-frags via ldmatrix.x4 from Ps[q][kv]) ----
#pragma unroll
    for (int ks = 0; ks < 8; ks++) {
      unsigned pa[4];
      int prow = wid * 16 + ((lane >> 3) & 1) * 8 + lrow;
      int pcol = ks * 8 + ((lane >> 4) << 2);
      ldsm4(pa, Ps + prow * 68 + pcol);
#pragma unroll
      for (int nt = 0; nt < 8; nt++) {
        unsigned bf[2];
        int n  = nt * 8 + g;
        int kk = ks * 8 + tg;
        bf[0] = VsP[kk * 72 + n];
        bf[1] = VsP[(kk + 4) * 72 + n];
        mma_tf32(oacc[nt], pa, bf);
      }
    }

    __syncthreads();
    if (kb + 2 < S_ / 64) stage(kb + 2, p);
    else cp_commit();
  }

  // epilogue: normalize, round to tf32 (final GEMM consumes raw)
  float inv0 = 1.f / l0, inv1 = 1.f / l1;
  int row = wid * 16 + g;
#pragma unroll
  for (int nt = 0; nt < 8; nt++) {
    int col = nt * 8 + 2 * tg;
    float2 o0 = make_float2(__uint_as_float(f2tf(oacc[nt][0] * inv0)),
                            __uint_as_float(f2tf(oacc[nt][1] * inv0)));
    float2 o1 = make_float2(__uint_as_float(f2tf(oacc[nt][2] * inv1)),
                            __uint_as_float(f2tf(oacc[nt][3] * inv1)));
    *(float2*)(Ob + (long)row * DM_ + col)       = o0;
    *(float2*)(Ob + (long)(row + 8) * DM_ + col) = o1;
  }
}

// ---------------------------------------------------------------------------
extern "C" void kernel_launch(void* const* d_in, const int* in_sizes, int n_in,
                              void* d_out, int out_size) {
  const float* x  = (const float*)d_in[0];
  const float* Wq = (const float*)d_in[1];
  const float* bq = (const float*)d_in[2];
  const float* Wk = (const float*)d_in[3];
  const float* bk = (const float*)d_in[4];
  const float* Wv = (const float*)d_in[5];
  const float* bv = (const float*)d_in[6];
  const float* Wo = (const float*)d_in[7];
  const float* bo = (const float*)d_in[8];
  float* out = (float*)d_out;

  float *q, *k, *v, *attn, *xt, *wqt, *wkt, *wvt, *wot;
  cudaGetSymbolAddress((void**)&q, g_q);
  cudaGetSymbolAddress((void**)&k, g_k);
  cudaGetSymbolAddress((void**)&v, g_v);
  cudaGetSymbolAddress((void**)&attn, g_attn);
  cudaGetSymbolAddress((void**)&xt, g_xt);
  cudaGetSymbolAddress((void**)&wqt, g_wqt);
  cudaGetSymbolAddress((void**)&wkt, g_wkt);
  cudaGetSymbolAddress((void**)&wvt, g_wvt);
  cudaGetSymbolAddress((void**)&wot, g_wot);

  tf32_round_kernel<<<512, 256>>>(x, xt, (long)MROWS * DM_ / 4);
  dim3 tgrid(DM_ / 32, DM_ / 32);
  tf32_roundT_kernel<<<tgrid, 256>>>(Wq, wqt);
  tf32_roundT_kernel<<<tgrid, 256>>>(Wk, wkt);
  tf32_roundT_kernel<<<tgrid, 256>>>(Wv, wvt);
  tf32_roundT_kernel<<<tgrid, 256>>>(Wo, wot);

  const int gemm_smem = 3 * GSTAGE_W * (int)sizeof(unsigned);  // 110592
  cudaFuncSetAttribute(gemm_qkv_kernel,
                       cudaFuncAttributeMaxDynamicSharedMemorySize, gemm_smem);
  cudaFuncSetAttribute(gemm_tc_kernel,
                       cudaFuncAttributeMaxDynamicSharedMemorySize, gemm_smem);

  dim3 qkvgrid(DM_ / 128, MROWS / 128, 3);
  gemm_qkv_kernel<<<qkvgrid, 256, gemm_smem>>>(xt, wqt, wkt, wvt, bq, bk, bv,
                                               q, k, v);

  const int flash_smem = (2 * 4352 + 2 * 4608 + 64 * 68) * (int)sizeof(unsigned);
  cudaFuncSetAttribute(flash_tc_kernel,
                       cudaFuncAttributeMaxDynamicSharedMemorySize, flash_smem);
  flash_tc_kernel<<<dim3(S_ / 64, B_ * H_), 128, flash_smem>>>(q, k, v, attn);

  dim3 ggrid(DM_ / 128, MROWS / 128);
  gemm_tc_kernel<<<ggrid, 256, gemm_smem>>>(attn, wot, bo, out, 0);
}

// round 6
// speedup vs baseline: 2.2939x; 2.2939x over previous
#include <cuda_runtime.h>
#include <cuda_fp16.h>
#include <math.h>

#define B_   2
#define S_   4096
#define DM_  1024
#define H_   16
#define HD_  64
#define MROWS (B_ * S_)

__device__ __half g_q[MROWS * DM_];
__device__ __half g_k[MROWS * DM_];
__device__ __half g_v[MROWS * DM_];
__device__ __half g_attn[MROWS * DM_];
__device__ __half g_xh[MROWS * DM_];
__device__ __half g_wqt[DM_ * DM_];
__device__ __half g_wkt[DM_ * DM_];
__device__ __half g_wvt[DM_ * DM_];
__device__ __half g_wot[DM_ * DM_];

__device__ __forceinline__ void mma_f16(float c[4], const unsigned a[4],
                                        const unsigned b[2]) {
  asm volatile(
      "mma.sync.aligned.m16n8k16.row.col.f32.f16.f16.f32 "
      "{%0,%1,%2,%3}, {%4,%5,%6,%7}, {%8,%9}, {%0,%1,%2,%3};"
      : "+f"(c[0]), "+f"(c[1]), "+f"(c[2]), "+f"(c[3])
      : "r"(a[0]), "r"(a[1]), "r"(a[2]), "r"(a[3]), "r"(b[0]), "r"(b[1]));
}

__device__ __forceinline__ void ldsm4(unsigned r[4], const void* p) {
  unsigned a = (unsigned)__cvta_generic_to_shared(p);
  asm volatile(
      "ldmatrix.sync.aligned.m8n8.x4.shared.b16 {%0,%1,%2,%3}, [%4];"
      : "=r"(r[0]), "=r"(r[1]), "=r"(r[2]), "=r"(r[3])
      : "r"(a));
}

__device__ __forceinline__ void ldsm4t(unsigned r[4], const void* p) {
  unsigned a = (unsigned)__cvta_generic_to_shared(p);
  asm volatile(
      "ldmatrix.sync.aligned.m8n8.x4.trans.shared.b16 {%0,%1,%2,%3}, [%4];"
      : "=r"(r[0]), "=r"(r[1]), "=r"(r[2]), "=r"(r[3])
      : "r"(a));
}

__device__ __forceinline__ void cp16(void* smem_dst, const void* gmem_src) {
  unsigned s = (unsigned)__cvta_generic_to_shared(smem_dst);
  asm volatile("cp.async.cg.shared.global [%0], [%1], 16;" ::"r"(s),
               "l"(gmem_src));
}
__device__ __forceinline__ void cp_commit() {
  asm volatile("cp.async.commit_group;");
}
__device__ __forceinline__ void cp_wait1() {
  asm volatile("cp.async.wait_group 1;");
}

__device__ __forceinline__ unsigned pack_h2(float lo, float hi) {
  __half2 h = __floats2half2_rn(lo, hi);
  return *(unsigned*)&h;
}

// ---------------------------------------------------------------------------
// Pre-pass: fp32 -> fp16 (x), and transpose + fp16 (weights).
// ---------------------------------------------------------------------------
__global__ void f2h_kernel(const float* __restrict__ in,
                           __half* __restrict__ out, long n4) {
  long i = (long)blockIdx.x * blockDim.x + threadIdx.x;
  long stride = (long)gridDim.x * blockDim.x;
  for (; i < n4; i += stride) {
    float4 v = ((const float4*)in)[i];
    ((__half2*)out)[2 * i]     = __floats2half2_rn(v.x, v.y);
    ((__half2*)out)[2 * i + 1] = __floats2half2_rn(v.z, v.w);
  }
}

// out[n*K + k] = half(in[k*N + n]); square DM_ x DM_.
__global__ __launch_bounds__(256) void f2hT_kernel(
    const float* __restrict__ in, __half* __restrict__ out) {
  __shared__ float t[32][33];
  int k0 = blockIdx.x * 32, n0 = blockIdx.y * 32;
  int tx = threadIdx.x & 31, ty = threadIdx.x >> 5;
#pragma unroll
  for (int i = 0; i < 32; i += 8)
    t[ty + i][tx] = in[(long)(k0 + ty + i) * DM_ + n0 + tx];
  __syncthreads();
#pragma unroll
  for (int i = 0; i < 32; i += 8)
    out[(long)(n0 + ty + i) * DM_ + k0 + tx] = __float2half_rn(t[tx][ty + i]);
}

// ---------------------------------------------------------------------------
// GEMM: C = A @ W + bias, A[M,K] half, W given TRANSPOSED (Wt[n][k] half).
// Tile 128x128x32, 2-stage cp.async (R4-proven pattern), ldmatrix frags,
// fp16 mma m16n8k16. OUTH: store half (scaled) else float.
// Smem: 2 stages x (As 128x40 + Bs 128x40) halves = 40960 B (static).
// ---------------------------------------------------------------------------
template <int OUTH>
__device__ __forceinline__ void gemm_body_h(
    const __half* __restrict__ A, const __half* __restrict__ Wt,
    const float* __restrict__ bias, void* Cv, float oscale, long m0, int n0) {
  __shared__ __half As[2][128 * 40];
  __shared__ __half Bs[2][128 * 40];

  const int tid  = threadIdx.x;
  const int lane = tid & 31;
  const int wid  = tid >> 5;
  const int g    = lane >> 2;
  const int tg   = lane & 3;
  const int wm   = wid & 3;
  const int wn   = wid >> 2;
  const int lrow = lane & 7;
  const int koct = ((lane >> 3) & 1) << 3;
  const int hoct = (lane >> 4) << 3;

  auto stage = [&](int k0, int buf) {
#pragma unroll
    for (int i = 0; i < 2; i++) {
      int idx = tid + i * 256;
      int r = idx >> 2, c = (idx & 3) * 8;
      cp16(&As[buf][r * 40 + c], A + (m0 + r) * DM_ + k0 + c);
      cp16(&Bs[buf][r * 40 + c], Wt + (long)(n0 + r) * DM_ + k0 + c);
    }
    cp_commit();
  };

  float acc[2][8][4];
#pragma unroll
  for (int mt = 0; mt < 2; mt++)
#pragma unroll
    for (int nt = 0; nt < 8; nt++)
#pragma unroll
      for (int j = 0; j < 4; j++) acc[mt][nt][j] = 0.f;

  stage(0, 0);
  stage(32, 1);

  const int NT = DM_ / 32;
  for (int kt = 0; kt < NT; kt++) {
    const int buf = kt & 1;
    cp_wait1();
    __syncthreads();

#pragma unroll
    for (int ksp = 0; ksp < 2; ksp++) {
      int k0 = ksp * 16;
      unsigned a[2][4];
#pragma unroll
      for (int mt = 0; mt < 2; mt++) {
        int row = wm * 32 + mt * 16 + koct + lrow;
        ldsm4(a[mt], &As[buf][row * 40 + k0 + hoct]);
      }
#pragma unroll
      for (int np = 0; np < 4; np++) {
        unsigned bb[4];
        int n = wn * 64 + np * 16 + hoct + lrow;
        ldsm4(bb, &Bs[buf][n * 40 + k0 + koct]);
        mma_f16(acc[0][2 * np],     a[0], bb);
        mma_f16(acc[0][2 * np + 1], a[0], bb + 2);
        mma_f16(acc[1][2 * np],     a[1], bb);
        mma_f16(acc[1][2 * np + 1], a[1], bb + 2);
      }
    }

    __syncthreads();
    if (kt + 2 < NT) stage((kt + 2) * 32, buf);
    else cp_commit();
  }

#pragma unroll
  for (int mt = 0; mt < 2; mt++) {
    long row = m0 + wm * 32 + mt * 16 + g;
#pragma unroll
    for (int nt = 0; nt < 8; nt++) {
      int col = n0 + wn * 64 + nt * 8 + 2 * tg;
      float2 bb = *(const float2*)(bias + col);
      float v00 = (acc[mt][nt][0] + bb.x) * oscale;
      float v01 = (acc[mt][nt][1] + bb.y) * oscale;
      float v10 = (acc[mt][nt][2] + bb.x) * oscale;
      float v11 = (acc[mt][nt][3] + bb.y) * oscale;
      if (OUTH) {
        __half* C = (__half*)Cv;
        *(__half2*)(C + row * DM_ + col)       = __floats2half2_rn(v00, v01);
        *(__half2*)(C + (row + 8) * DM_ + col) = __floats2half2_rn(v10, v11);
      } else {
        float* C = (float*)Cv;
        *(float2*)(C + row * DM_ + col)       = make_float2(v00, v01);
        *(float2*)(C + (row + 8) * DM_ + col) = make_float2(v10, v11);
      }
    }
  }
}

// (1/sqrt(64)) * log2(e) — folded into Q at projection time (exp2 softmax)
#define QSCALE 0.18033688011112042592f

__global__ __launch_bounds__(256) void gemm_qkv_kernel(
    const __half* __restrict__ A, const __half* __restrict__ Wqt,
    const __half* __restrict__ Wkt, const __half* __restrict__ Wvt,
    const float* __restrict__ bq, const float* __restrict__ bk,
    const float* __restrict__ bv, __half* __restrict__ Qo,
    __half* __restrict__ Ko, __half* __restrict__ Vo) {
  const __half* Wt = (blockIdx.z == 0) ? Wqt : (blockIdx.z == 1) ? Wkt : Wvt;
  const float* bias = (blockIdx.z == 0) ? bq : (blockIdx.z == 1) ? bk : bv;
  __half* C = (blockIdx.z == 0) ? Qo : (blockIdx.z == 1) ? Ko : Vo;
  float sc = (blockIdx.z == 0) ? QSCALE : 1.0f;
  gemm_body_h<1>(A, Wt, bias, C, sc, (long)blockIdx.y * 128, blockIdx.x * 128);
}

__global__ __launch_bounds__(256) void gemm_out_kernel(
    const __half* __restrict__ A, const __half* __restrict__ Wt,
    const float* __restrict__ bias, float* __restrict__ C) {
  gemm_body_h<0>(A, Wt, bias, C, 1.0f, (long)blockIdx.y * 128,
                 blockIdx.x * 128);
}

// ---------------------------------------------------------------------------
// Flash attention, fp16 mma. CTA: 128 threads (4 warps), 64 q rows.
// Q pre-scaled; K frags via ldmatrix, V via ldmatrix.trans; P stays in
// registers (S-frag layout == PV A-frag layout for fp16).
// Smem: 2 x (Ks 64x72 + Vs 64x72) halves = 36864 B (static).
// ---------------------------------------------------------------------------
__global__ __launch_bounds__(128) void flash_h_kernel(
    const __half* __restrict__ Qg, const __half* __restrict__ Kg,
    const __half* __restrict__ Vg, __half* __restrict__ Og) {
  __shared__ __half Ks[2][64 * 72];
  __shared__ __half Vs[2][64 * 72];

  const int tid  = threadIdx.x;
  const int lane = tid & 31;
  const int wid  = tid >> 5;
  const int g    = lane >> 2;
  const int tg   = lane & 3;
  const int lrow = lane & 7;
  const int koct = ((lane >> 3) & 1) << 3;
  const int hoct = (lane >> 4) << 3;
  const int bh   = blockIdx.y;
  const int b    = bh >> 4;
  const int h    = bh & 15;
  const int q0   = blockIdx.x * 64;

  const __half* Qb  = Qg + ((long)(b * S_ + q0)) * DM_ + h * HD_;
  const __half* Kb0 = Kg + ((long)b * S_) * DM_ + h * HD_;
  const __half* Vb0 = Vg + ((long)b * S_) * DM_ + h * HD_;
  __half* Ob        = Og + ((long)(b * S_ + q0)) * DM_ + h * HD_;

  auto stage = [&](int kb, int p) {
    const __half* Kb = Kb0 + (long)(kb * 64) * DM_;
    const __half* Vb = Vb0 + (long)(kb * 64) * DM_;
#pragma unroll
    for (int i = 0; i < 4; i++) {
      int idx = tid + i * 128;
      int kv = idx >> 3, c = (idx & 7) * 8;
      cp16(&Ks[p][kv * 72 + c], Kb + (long)kv * DM_ + c);
      cp16(&Vs[p][kv * 72 + c], Vb + (long)kv * DM_ + c);
    }
    cp_commit();
  };

  // Q A-fragments (pre-scaled halves straight from gmem)
  unsigned qa[4][4];
  {
    int qrow = wid * 16 + g;
#pragma unroll
    for (int ks = 0; ks < 4; ks++) {
      int c = ks * 16 + 2 * tg;
      qa[ks][0] = *(const unsigned*)(Qb + (long)qrow * DM_ + c);
      qa[ks][1] = *(const unsigned*)(Qb + (long)(qrow + 8) * DM_ + c);
      qa[ks][2] = *(const unsigned*)(Qb + (long)qrow * DM_ + c + 8);
      qa[ks][3] = *(const unsigned*)(Qb + (long)(qrow + 8) * DM_ + c + 8);
    }
  }

  float oacc[8][4];
#pragma unroll
  for (int nt = 0; nt < 8; nt++)
#pragma unroll
    for (int j = 0; j < 4; j++) oacc[nt][j] = 0.f;
  float m0r = -INFINITY, m1r = -INFINITY, l0 = 0.f, l1 = 0.f;

  stage(0, 0);
  stage(1, 1);

  for (int kb = 0; kb < S_ / 64; kb++) {
    const int p = kb & 1;
    cp_wait1();
    __syncthreads();

    // ---- S = Q K^T ----
    float sacc[8][4];
#pragma unroll
    for (int nt = 0; nt < 8; nt++)
#pragma unroll
      for (int j = 0; j < 4; j++) sacc[nt][j] = 0.f;
#pragma unroll
    for (int np = 0; np < 4; np++) {
#pragma unroll
      for (int ks = 0; ks < 4; ks++) {
        unsigned bb[4];
        int n = np * 16 + hoct + lrow;
        ldsm4(bb, &Ks[p][n * 72 + ks * 16 + koct]);
        mma_f16(sacc[2 * np],     qa[ks], bb);
        mma_f16(sacc[2 * np + 1], qa[ks], bb + 2);
      }
    }

    // ---- online softmax (exp2 domain; scale folded into Q) ----
    float mx0 = -INFINITY, mx1 = -INFINITY;
#pragma unroll
    for (int nt = 0; nt < 8; nt++) {
      mx0 = fmaxf(mx0, fmaxf(sacc[nt][0], sacc[nt][1]));
      mx1 = fmaxf(mx1, fmaxf(sacc[nt][2], sacc[nt][3]));
    }
#pragma unroll
    for (int off = 1; off <= 2; off <<= 1) {
      mx0 = fmaxf(mx0, __shfl_xor_sync(0xffffffffu, mx0, off));
      mx1 = fmaxf(mx1, __shfl_xor_sync(0xffffffffu, mx1, off));
    }
    float mn0 = fmaxf(m0r, mx0), mn1 = fmaxf(m1r, mx1);
    float al0 = exp2f(m0r - mn0), al1 = exp2f(m1r - mn1);
    m0r = mn0; m1r = mn1;

    float ps0 = 0.f, ps1 = 0.f;
#pragma unroll
    for (int nt = 0; nt < 8; nt++) {
      sacc[nt][0] = exp2f(sacc[nt][0] - mn0);
      sacc[nt][1] = exp2f(sacc[nt][1] - mn0);
      sacc[nt][2] = exp2f(sacc[nt][2] - mn1);
      sacc[nt][3] = exp2f(sacc[nt][3] - mn1);
      ps0 += sacc[nt][0] + sacc[nt][1];
      ps1 += sacc[nt][2] + sacc[nt][3];
    }
#pragma unroll
    for (int off = 1; off <= 2; off <<= 1) {
      ps0 += __shfl_xor_sync(0xffffffffu, ps0, off);
      ps1 += __shfl_xor_sync(0xffffffffu, ps1, off);
    }
    l0 = l0 * al0 + ps0;
    l1 = l1 * al1 + ps1;
#pragma unroll
    for (int nt = 0; nt < 8; nt++) {
      oacc[nt][0] *= al0;
      oacc[nt][1] *= al0;
      oacc[nt][2] *= al1;
      oacc[nt][3] *= al1;
    }

    // ---- P fragments directly from S accumulators (no smem) ----
    unsigned pa[4][4];
#pragma unroll
    for (int ks = 0; ks < 4; ks++) {
      pa[ks][0] = pack_h2(sacc[2 * ks][0],     sacc[2 * ks][1]);
      pa[ks][1] = pack_h2(sacc[2 * ks][2],     sacc[2 * ks][3]);
      pa[ks][2] = pack_h2(sacc[2 * ks + 1][0], sacc[2 * ks + 1][1]);
      pa[ks][3] = pack_h2(sacc[2 * ks + 1][2], sacc[2 * ks + 1][3]);
    }

    // ---- O += P V (V fragments via ldmatrix.trans) ----
#pragma unroll
    for (int ks = 0; ks < 4; ks++) {
#pragma unroll
      for (int dp = 0; dp < 4; dp++) {
        unsigned vv[4];
        int kv = ks * 16 + koct + lrow;
        int d  = dp * 16 + hoct;
        ldsm4t(vv, &Vs[p][kv * 72 + d]);
        mma_f16(oacc[2 * dp],     pa[ks], vv);
        mma_f16(oacc[2 * dp + 1], pa[ks], vv + 2);
      }
    }

    __syncthreads();
    if (kb + 2 < S_ / 64) stage(kb + 2, p);
    else cp_commit();
  }

  // epilogue: normalize, store half (final GEMM input)
  float inv0 = 1.f / l0, inv1 = 1.f / l1;
  int row = wid * 16 + g;
#pragma unroll
  for (int nt = 0; nt < 8; nt++) {
    int col = nt * 8 + 2 * tg;
    *(__half2*)(Ob + (long)row * DM_ + col) =
        __floats2half2_rn(oacc[nt][0] * inv0, oacc[nt][1] * inv0);
    *(__half2*)(Ob + (long)(row + 8) * DM_ + col) =
        __floats2half2_rn(oacc[nt][2] * inv1, oacc[nt][3] * inv1);
  }
}

// ---------------------------------------------------------------------------
extern "C" void kernel_launch(void* const* d_in, const int* in_sizes, int n_in,
                              void* d_out, int out_size) {
  const float* x  = (const float*)d_in[0];
  const float* Wq = (const float*)d_in[1];
  const float* bq = (const float*)d_in[2];
  const float* Wk = (const float*)d_in[3];
  const float* bk = (const float*)d_in[4];
  const float* Wv = (const float*)d_in[5];
  const float* bv = (const float*)d_in[6];
  const float* Wo = (const float*)d_in[7];
  const float* bo = (const float*)d_in[8];
  float* out = (float*)d_out;

  __half *q, *k, *v, *attn, *xh, *wqt, *wkt, *wvt, *wot;
  cudaGetSymbolAddress((void**)&q, g_q);
  cudaGetSymbolAddress((void**)&k, g_k);
  cudaGetSymbolAddress((void**)&v, g_v);
  cudaGetSymbolAddress((void**)&attn, g_attn);
  cudaGetSymbolAddress((void**)&xh, g_xh);
  cudaGetSymbolAddress((void**)&wqt, g_wqt);
  cudaGetSymbolAddress((void**)&wkt, g_wkt);
  cudaGetSymbolAddress((void**)&wvt, g_wvt);
  cudaGetSymbolAddress((void**)&wot, g_wot);

  f2h_kernel<<<512, 256>>>(x, xh, (long)MROWS * DM_ / 4);
  dim3 tgrid(DM_ / 32, DM_ / 32);
  f2hT_kernel<<<tgrid, 256>>>(Wq, wqt);
  f2hT_kernel<<<tgrid, 256>>>(Wk, wkt);
  f2hT_kernel<<<tgrid, 256>>>(Wv, wvt);
  f2hT_kernel<<<tgrid, 256>>>(Wo, wot);

  dim3 qkvgrid(DM_ / 128, MROWS / 128, 3);
  gemm_qkv_kernel<<<qkvgrid, 256>>>(xh, wqt, wkt, wvt, bq, bk, bv, q, k, v);

  flash_h_kernel<<<dim3(S_ / 64, B_ * H_), 128>>>(q, k, v, attn);

  dim3 ggrid(DM_ / 128, MROWS / 128);
  gemm_out_kernel<<<ggrid, 256>>>(attn, wot, bo, out);
}

// round 8
// speedup vs baseline: 2.3394x; 1.0198x over previous
#include <cuda_runtime.h>
#include <cuda_fp16.h>
#include <math.h>

#define B_   2
#define S_   4096
#define DM_  1024
#define H_   16
#define HD_  64
#define MROWS (B_ * S_)

__device__ __half g_q[MROWS * DM_];
__device__ __half g_k[MROWS * DM_];
__device__ __half g_v[MROWS * DM_];
__device__ __half g_attn[MROWS * DM_];
__device__ __half g_xh[MROWS * DM_];
__device__ __half g_wqt[DM_ * DM_];
__device__ __half g_wkt[DM_ * DM_];
__device__ __half g_wvt[DM_ * DM_];
__device__ __half g_wot[DM_ * DM_];

__device__ __forceinline__ void mma_f16(float c[4], const unsigned a[4],
                                        const unsigned b[2]) {
  asm volatile(
      "mma.sync.aligned.m16n8k16.row.col.f32.f16.f16.f32 "
      "{%0,%1,%2,%3}, {%4,%5,%6,%7}, {%8,%9}, {%0,%1,%2,%3};"
      : "+f"(c[0]), "+f"(c[1]), "+f"(c[2]), "+f"(c[3])
      : "r"(a[0]), "r"(a[1]), "r"(a[2]), "r"(a[3]), "r"(b[0]), "r"(b[1]));
}

__device__ __forceinline__ void ldsm4(unsigned r[4], const void* p) {
  unsigned a = (unsigned)__cvta_generic_to_shared(p);
  asm volatile(
      "ldmatrix.sync.aligned.m8n8.x4.shared.b16 {%0,%1,%2,%3}, [%4];"
      : "=r"(r[0]), "=r"(r[1]), "=r"(r[2]), "=r"(r[3])
      : "r"(a));
}

__device__ __forceinline__ void ldsm4t(unsigned r[4], const void* p) {
  unsigned a = (unsigned)__cvta_generic_to_shared(p);
  asm volatile(
      "ldmatrix.sync.aligned.m8n8.x4.trans.shared.b16 {%0,%1,%2,%3}, [%4];"
      : "=r"(r[0]), "=r"(r[1]), "=r"(r[2]), "=r"(r[3])
      : "r"(a));
}

__device__ __forceinline__ void cp16(void* smem_dst, const void* gmem_src) {
  unsigned s = (unsigned)__cvta_generic_to_shared(smem_dst);
  asm volatile("cp.async.cg.shared.global [%0], [%1], 16;" ::"r"(s),
               "l"(gmem_src));
}
__device__ __forceinline__ void cp_commit() {
  asm volatile("cp.async.commit_group;");
}
__device__ __forceinline__ void cp_wait1() {
  asm volatile("cp.async.wait_group 1;");
}

__device__ __forceinline__ unsigned pack_h2(float lo, float hi) {
  __half2 h = __floats2half2_rn(lo, hi);
  return *(unsigned*)&h;
}

// ---------------------------------------------------------------------------
// Pre-pass: fp32 -> fp16 (x), and transpose + fp16 (weights).
// ---------------------------------------------------------------------------
__global__ void f2h_kernel(const float* __restrict__ in,
                           __half* __restrict__ out, long n4) {
  long i = (long)blockIdx.x * blockDim.x + threadIdx.x;
  long stride = (long)gridDim.x * blockDim.x;
  for (; i < n4; i += stride) {
    float4 v = ((const float4*)in)[i];
    ((__half2*)out)[2 * i]     = __floats2half2_rn(v.x, v.y);
    ((__half2*)out)[2 * i + 1] = __floats2half2_rn(v.z, v.w);
  }
}

__global__ __launch_bounds__(256) void f2hT_kernel(
    const float* __restrict__ in, __half* __restrict__ out) {
  __shared__ float t[32][33];
  int k0 = blockIdx.x * 32, n0 = blockIdx.y * 32;
  int tx = threadIdx.x & 31, ty = threadIdx.x >> 5;
#pragma unroll
  for (int i = 0; i < 32; i += 8)
    t[ty + i][tx] = in[(long)(k0 + ty + i) * DM_ + n0 + tx];
  __syncthreads();
#pragma unroll
  for (int i = 0; i < 32; i += 8)
    out[(long)(n0 + ty + i) * DM_ + k0 + tx] = __float2half_rn(t[tx][ty + i]);
}

// ---------------------------------------------------------------------------
// GEMM: C = A @ W + bias, A[M,K] half, Wt[n][k] half (pre-transposed).
// Tile 128x128, K staged 64 at a time (half the syncs of R6), 2-stage
// cp.async, ldmatrix frags, fp16 mma m16n8k16.
// Dynamic smem: 2 stages x (A 128x72 + B 128x72) halves = 73728 B.
// ---------------------------------------------------------------------------
#define GST 9216  // halves per (matrix, stage): 128*72

template <int OUTH>
__device__ __forceinline__ void gemm_body_h(
    const __half* __restrict__ A, const __half* __restrict__ Wt,
    const float* __restrict__ bias, void* Cv, float oscale, long m0, int n0) {
  extern __shared__ __half gsm[];
  __half* As = gsm;             // [2][128*72]
  __half* Bs = gsm + 2 * GST;   // [2][128*72]

  const int tid  = threadIdx.x;
  const int lane = tid & 31;
  const int wid  = tid >> 5;
  const int g    = lane >> 2;
  const int tg   = lane & 3;
  const int wm   = wid & 3;
  const int wn   = wid >> 2;
  const int lrow = lane & 7;
  const int koct = ((lane >> 3) & 1) << 3;
  const int hoct = (lane >> 4) << 3;

  auto stage = [&](int k0, int buf) {
#pragma unroll
    for (int i = 0; i < 4; i++) {
      int idx = tid + i * 256;
      int r = idx >> 3, c = (idx & 7) * 8;
      cp16(&As[buf * GST + r * 72 + c], A + (m0 + r) * DM_ + k0 + c);
      cp16(&Bs[buf * GST + r * 72 + c], Wt + (long)(n0 + r) * DM_ + k0 + c);
    }
    cp_commit();
  };

  float acc[2][8][4];
#pragma unroll
  for (int mt = 0; mt < 2; mt++)
#pragma unroll
    for (int nt = 0; nt < 8; nt++)
#pragma unroll
      for (int j = 0; j < 4; j++) acc[mt][nt][j] = 0.f;

  stage(0, 0);
  stage(64, 1);

  const int NT = DM_ / 64;  // 16
  for (int kt = 0; kt < NT; kt++) {
    const int buf = kt & 1;
    cp_wait1();
    __syncthreads();
    const __half* Ab = As + buf * GST;
    const __half* Bb = Bs + buf * GST;

#pragma unroll
    for (int ksp = 0; ksp < 4; ksp++) {
      int k0 = ksp * 16;
      unsigned a[2][4];
#pragma unroll
      for (int mt = 0; mt < 2; mt++) {
        int row = wm * 32 + mt * 16 + koct + lrow;
        ldsm4(a[mt], Ab + row * 72 + k0 + hoct);
      }
#pragma unroll
      for (int np = 0; np < 4; np++) {
        unsigned bb[4];
        int n = wn * 64 + np * 16 + hoct + lrow;
        ldsm4(bb, Bb + n * 72 + k0 + koct);
        mma_f16(acc[0][2 * np],     a[0], bb);
        mma_f16(acc[0][2 * np + 1], a[0], bb + 2);
        mma_f16(acc[1][2 * np],     a[1], bb);
        mma_f16(acc[1][2 * np + 1], a[1], bb + 2);
      }
    }

    __syncthreads();
    if (kt + 2 < NT) stage((kt + 2) * 64, buf);
    else cp_commit();
  }

#pragma unroll
  for (int mt = 0; mt < 2; mt++) {
    long row = m0 + wm * 32 + mt * 16 + g;
#pragma unroll
    for (int nt = 0; nt < 8; nt++) {
      int col = n0 + wn * 64 + nt * 8 + 2 * tg;
      float2 bb = *(const float2*)(bias + col);
      float v00 = (acc[mt][nt][0] + bb.x) * oscale;
      float v01 = (acc[mt][nt][1] + bb.y) * oscale;
      float v10 = (acc[mt][nt][2] + bb.x) * oscale;
      float v11 = (acc[mt][nt][3] + bb.y) * oscale;
      if (OUTH) {
        __half* C = (__half*)Cv;
        *(__half2*)(C + row * DM_ + col)       = __floats2half2_rn(v00, v01);
        *(__half2*)(C + (row + 8) * DM_ + col) = __floats2half2_rn(v10, v11);
      } else {
        float* C = (float*)Cv;
        *(float2*)(C + row * DM_ + col)       = make_float2(v00, v01);
        *(float2*)(C + (row + 8) * DM_ + col) = make_float2(v10, v11);
      }
    }
  }
}

#define QSCALE 0.18033688011112042592f  // (1/sqrt(64)) * log2(e)
#define GEMM_SMEM (4 * GST * 2)         // 73728 B

__global__ __launch_bounds__(256) void gemm_qkv_kernel(
    const __half* __restrict__ A, const __half* __restrict__ Wqt,
    const __half* __restrict__ Wkt, const __half* __restrict__ Wvt,
    const float* __restrict__ bq, const float* __restrict__ bk,
    const float* __restrict__ bv, __half* __restrict__ Qo,
    __half* __restrict__ Ko, __half* __restrict__ Vo) {
  const __half* Wt = (blockIdx.z == 0) ? Wqt : (blockIdx.z == 1) ? Wkt : Wvt;
  const float* bias = (blockIdx.z == 0) ? bq : (blockIdx.z == 1) ? bk : bv;
  __half* C = (blockIdx.z == 0) ? Qo : (blockIdx.z == 1) ? Ko : Vo;
  float sc = (blockIdx.z == 0) ? QSCALE : 1.0f;
  gemm_body_h<1>(A, Wt, bias, C, sc, (long)blockIdx.y * 128, blockIdx.x * 128);
}

__global__ __launch_bounds__(256) void gemm_out_kernel(
    const __half* __restrict__ A, const __half* __restrict__ Wt,
    const float* __restrict__ bias, float* __restrict__ C) {
  gemm_body_h<0>(A, Wt, bias, C, 1.0f, (long)blockIdx.y * 128,
                 blockIdx.x * 128);
}

// ---------------------------------------------------------------------------
// Flash attention, fp16 mma — UNCHANGED from R6 (697us best).
// ---------------------------------------------------------------------------
__global__ __launch_bounds__(128) void flash_h_kernel(
    const __half* __restrict__ Qg, const __half* __restrict__ Kg,
    const __half* __restrict__ Vg, __half* __restrict__ Og) {
  __shared__ __half Ks[2][64 * 72];
  __shared__ __half Vs[2][64 * 72];

  const int tid  = threadIdx.x;
  const int lane = tid & 31;
  const int wid  = tid >> 5;
  const int g    = lane >> 2;
  const int tg   = lane & 3;
  const int lrow = lane & 7;
  const int koct = ((lane >> 3) & 1) << 3;
  const int hoct = (lane >> 4) << 3;
  const int bh   = blockIdx.y;
  const int b    = bh >> 4;
  const int h    = bh & 15;
  const int q0   = blockIdx.x * 64;

  const __half* Qb  = Qg + ((long)(b * S_ + q0)) * DM_ + h * HD_;
  const __half* Kb0 = Kg + ((long)b * S_) * DM_ + h * HD_;
  const __half* Vb0 = Vg + ((long)b * S_) * DM_ + h * HD_;
  __half* Ob        = Og + ((long)(b * S_ + q0)) * DM_ + h * HD_;

  auto stage = [&](int kb, int p) {
    const __half* Kb = Kb0 + (long)(kb * 64) * DM_;
    const __half* Vb = Vb0 + (long)(kb * 64) * DM_;
#pragma unroll
    for (int i = 0; i < 4; i++) {
      int idx = tid + i * 128;
      int kv = idx >> 3, c = (idx & 7) * 8;
      cp16(&Ks[p][kv * 72 + c], Kb + (long)kv * DM_ + c);
      cp16(&Vs[p][kv * 72 + c], Vb + (long)kv * DM_ + c);
    }
    cp_commit();
  };

  unsigned qa[4][4];
  {
    int qrow = wid * 16 + g;
#pragma unroll
    for (int ks = 0; ks < 4; ks++) {
      int c = ks * 16 + 2 * tg;
      qa[ks][0] = *(const unsigned*)(Qb + (long)qrow * DM_ + c);
      qa[ks][1] = *(const unsigned*)(Qb + (long)(qrow + 8) * DM_ + c);
      qa[ks][2] = *(const unsigned*)(Qb + (long)qrow * DM_ + c + 8);
      qa[ks][3] = *(const unsigned*)(Qb + (long)(qrow + 8) * DM_ + c + 8);
    }
  }

  float oacc[8][4];
#pragma unroll
  for (int nt = 0; nt < 8; nt++)
#pragma unroll
    for (int j = 0; j < 4; j++) oacc[nt][j] = 0.f;
  float m0r = -INFINITY, m1r = -INFINITY, l0 = 0.f, l1 = 0.f;

  stage(0, 0);
  stage(1, 1);

  for (int kb = 0; kb < S_ / 64; kb++) {
    const int p = kb & 1;
    cp_wait1();
    __syncthreads();

    float sacc[8][4];
#pragma unroll
    for (int nt = 0; nt < 8; nt++)
#pragma unroll
      for (int j = 0; j < 4; j++) sacc[nt][j] = 0.f;
#pragma unroll
    for (int np = 0; np < 4; np++) {
#pragma unroll
      for (int ks = 0; ks < 4; ks++) {
        unsigned bb[4];
        int n = np * 16 + hoct + lrow;
        ldsm4(bb, &Ks[p][n * 72 + ks * 16 + koct]);
        mma_f16(sacc[2 * np],     qa[ks], bb);
        mma_f16(sacc[2 * np + 1], qa[ks], bb + 2);
      }
    }

    float mx0 = -INFINITY, mx1 = -INFINITY;
#pragma unroll
    for (int nt = 0; nt < 8; nt++) {
      mx0 = fmaxf(mx0, fmaxf(sacc[nt][0], sacc[nt][1]));
      mx1 = fmaxf(mx1, fmaxf(sacc[nt][2], sacc[nt][3]));
    }
#pragma unroll
    for (int off = 1; off <= 2; off <<= 1) {
      mx0 = fmaxf(mx0, __shfl_xor_sync(0xffffffffu, mx0, off));
      mx1 = fmaxf(mx1, __shfl_xor_sync(0xffffffffu, mx1, off));
    }
    float mn0 = fmaxf(m0r, mx0), mn1 = fmaxf(m1r, mx1);
    float al0 = exp2f(m0r - mn0), al1 = exp2f(m1r - mn1);
    m0r = mn0; m1r = mn1;

    float ps0 = 0.f, ps1 = 0.f;
#pragma unroll
    for (int nt = 0; nt < 8; nt++) {
      sacc[nt][0] = exp2f(sacc[nt][0] - mn0);
      sacc[nt][1] = exp2f(sacc[nt][1] - mn0);
      sacc[nt][2] = exp2f(sacc[nt][2] - mn1);
      sacc[nt][3] = exp2f(sacc[nt][3] - mn1);
      ps0 += sacc[nt][0] + sacc[nt][1];
      ps1 += sacc[nt][2] + sacc[nt][3];
    }
#pragma unroll
    for (int off = 1; off <= 2; off <<= 1) {
      ps0 += __shfl_xor_sync(0xffffffffu, ps0, off);
      ps1 += __shfl_xor_sync(0xffffffffu, ps1, off);
    }
    l0 = l0 * al0 + ps0;
    l1 = l1 * al1 + ps1;
#pragma unroll
    for (int nt = 0; nt < 8; nt++) {
      oacc[nt][0] *= al0;
      oacc[nt][1] *= al0;
      oacc[nt][2] *= al1;
      oacc[nt][3] *= al1;
    }

    unsigned pa[4][4];
#pragma unroll
    for (int ks = 0; ks < 4; ks++) {
      pa[ks][0] = pack_h2(sacc[2 * ks][0],     sacc[2 * ks][1]);
      pa[ks][1] = pack_h2(sacc[2 * ks][2],     sacc[2 * ks][3]);
      pa[ks][2] = pack_h2(sacc[2 * ks + 1][0], sacc[2 * ks + 1][1]);
      pa[ks][3] = pack_h2(sacc[2 * ks + 1][2], sacc[2 * ks + 1][3]);
    }

#pragma unroll
    for (int ks = 0; ks < 4; ks++) {
#pragma unroll
      for (int dp = 0; dp < 4; dp++) {
        unsigned vv[4];
        int kv = ks * 16 + koct + lrow;
        int d  = dp * 16 + hoct;
        ldsm4t(vv, &Vs[p][kv * 72 + d]);
        mma_f16(oacc[2 * dp],     pa[ks], vv);
        mma_f16(oacc[2 * dp + 1], pa[ks], vv + 2);
      }
    }

    __syncthreads();
    if (kb + 2 < S_ / 64) stage(kb + 2, p);
    else cp_commit();
  }

  float inv0 = 1.f / l0, inv1 = 1.f / l1;
  int row = wid * 16 + g;
#pragma unroll
  for (int nt = 0; nt < 8; nt++) {
    int col = nt * 8 + 2 * tg;
    *(__half2*)(Ob + (long)row * DM_ + col) =
        __floats2half2_rn(oacc[nt][0] * inv0, oacc[nt][1] * inv0);
    *(__half2*)(Ob + (long)(row + 8) * DM_ + col) =
        __floats2half2_rn(oacc[nt][2] * inv1, oacc[nt][3] * inv1);
  }
}

// ---------------------------------------------------------------------------
extern "C" void kernel_launch(void* const* d_in, const int* in_sizes, int n_in,
                              void* d_out, int out_size) {
  const float* x  = (const float*)d_in[0];
  const float* Wq = (const float*)d_in[1];
  const float* bq = (const float*)d_in[2];
  const float* Wk = (const float*)d_in[3];
  const float* bk = (const float*)d_in[4];
  const float* Wv = (const float*)d_in[5];
  const float* bv = (const float*)d_in[6];
  const float* Wo = (const float*)d_in[7];
  const float* bo = (const float*)d_in[8];
  float* out = (float*)d_out;

  __half *q, *k, *v, *attn, *xh, *wqt, *wkt, *wvt, *wot;
  cudaGetSymbolAddress((void**)&q, g_q);
  cudaGetSymbolAddress((void**)&k, g_k);
  cudaGetSymbolAddress((void**)&v, g_v);
  cudaGetSymbolAddress((void**)&attn, g_attn);
  cudaGetSymbolAddress((void**)&xh, g_xh);
  cudaGetSymbolAddress((void**)&wqt, g_wqt);
  cudaGetSymbolAddress((void**)&wkt, g_wkt);
  cudaGetSymbolAddress((void**)&wvt, g_wvt);
  cudaGetSymbolAddress((void**)&wot, g_wot);

  f2h_kernel<<<512, 256>>>(x, xh, (long)MROWS * DM_ / 4);
  dim3 tgrid(DM_ / 32, DM_ / 32);
  f2hT_kernel<<<tgrid, 256>>>(Wq, wqt);
  f2hT_kernel<<<tgrid, 256>>>(Wk, wkt);
  f2hT_kernel<<<tgrid, 256>>>(Wv, wvt);
  f2hT_kernel<<<tgrid, 256>>>(Wo, wot);

  cudaFuncSetAttribute(gemm_qkv_kernel,
                       cudaFuncAttributeMaxDynamicSharedMemorySize, GEMM_SMEM);
  cudaFuncSetAttribute(gemm_out_kernel,
                       cudaFuncAttributeMaxDynamicSharedMemorySize, GEMM_SMEM);

  dim3 qkvgrid(DM_ / 128, MROWS / 128, 3);
  gemm_qkv_kernel<<<qkvgrid, 256, GEMM_SMEM>>>(xh, wqt, wkt, wvt, bq, bk, bv,
                                               q, k, v);

  flash_h_kernel<<<dim3(S_ / 64, B_ * H_), 128>>>(q, k, v, attn);

  dim3 ggrid(DM_ / 128, MROWS / 128);
  gemm_out_kernel<<<ggrid, 256, GEMM_SMEM>>>(attn, wot, bo, out);
}

// round 9
// speedup vs baseline: 2.4263x; 1.0372x over previous
#include <cuda_runtime.h>
#include <cuda_fp16.h>
#include <math.h>

#define B_   2
#define S_   4096
#define DM_  1024
#define H_   16
#define HD_  64
#define MROWS (B_ * S_)

__device__ __half g_q[MROWS * DM_];
__device__ __half g_k[MROWS * DM_];
__device__ __half g_v[MROWS * DM_];
__device__ __half g_attn[MROWS * DM_];
__device__ __half g_xh[MROWS * DM_];
__device__ __half g_wqt[DM_ * DM_];
__device__ __half g_wkt[DM_ * DM_];
__device__ __half g_wvt[DM_ * DM_];
__device__ __half g_wot[DM_ * DM_];

__device__ __forceinline__ void mma_f16(float c[4], const unsigned a[4],
                                        const unsigned b[2]) {
  asm volatile(
      "mma.sync.aligned.m16n8k16.row.col.f32.f16.f16.f32 "
      "{%0,%1,%2,%3}, {%4,%5,%6,%7}, {%8,%9}, {%0,%1,%2,%3};"
      : "+f"(c[0]), "+f"(c[1]), "+f"(c[2]), "+f"(c[3])
      : "r"(a[0]), "r"(a[1]), "r"(a[2]), "r"(a[3]), "r"(b[0]), "r"(b[1]));
}

__device__ __forceinline__ void ldsm4(unsigned r[4], const void* p) {
  unsigned a = (unsigned)__cvta_generic_to_shared(p);
  asm volatile(
      "ldmatrix.sync.aligned.m8n8.x4.shared.b16 {%0,%1,%2,%3}, [%4];"
      : "=r"(r[0]), "=r"(r[1]), "=r"(r[2]), "=r"(r[3])
      : "r"(a));
}

__device__ __forceinline__ void ldsm4t(unsigned r[4], const void* p) {
  unsigned a = (unsigned)__cvta_generic_to_shared(p);
  asm volatile(
      "ldmatrix.sync.aligned.m8n8.x4.trans.shared.b16 {%0,%1,%2,%3}, [%4];"
      : "=r"(r[0]), "=r"(r[1]), "=r"(r[2]), "=r"(r[3])
      : "r"(a));
}

__device__ __forceinline__ void cp16(void* smem_dst, const void* gmem_src) {
  unsigned s = (unsigned)__cvta_generic_to_shared(smem_dst);
  asm volatile("cp.async.cg.shared.global [%0], [%1], 16;" ::"r"(s),
               "l"(gmem_src));
}
__device__ __forceinline__ void cp_commit() {
  asm volatile("cp.async.commit_group;");
}
__device__ __forceinline__ void cp_wait1() {
  asm volatile("cp.async.wait_group 1;");
}

__device__ __forceinline__ unsigned pack_h2(float lo, float hi) {
  __half2 h = __floats2half2_rn(lo, hi);
  return *(unsigned*)&h;
}

// ---------------------------------------------------------------------------
// Pre-pass: fp32 -> fp16 (x), and transpose + fp16 (weights).
// ---------------------------------------------------------------------------
__global__ void f2h_kernel(const float* __restrict__ in,
                           __half* __restrict__ out, long n4) {
  long i = (long)blockIdx.x * blockDim.x + threadIdx.x;
  long stride = (long)gridDim.x * blockDim.x;
  for (; i < n4; i += stride) {
    float4 v = ((const float4*)in)[i];
    ((__half2*)out)[2 * i]     = __floats2half2_rn(v.x, v.y);
    ((__half2*)out)[2 * i + 1] = __floats2half2_rn(v.z, v.w);
  }
}

__global__ __launch_bounds__(256) void f2hT_kernel(
    const float* __restrict__ in, __half* __restrict__ out) {
  __shared__ float t[32][33];
  int k0 = blockIdx.x * 32, n0 = blockIdx.y * 32;
  int tx = threadIdx.x & 31, ty = threadIdx.x >> 5;
#pragma unroll
  for (int i = 0; i < 32; i += 8)
    t[ty + i][tx] = in[(long)(k0 + ty + i) * DM_ + n0 + tx];
  __syncthreads();
#pragma unroll
  for (int i = 0; i < 32; i += 8)
    out[(long)(n0 + ty + i) * DM_ + k0 + tx] = __float2half_rn(t[tx][ty + i]);
}

// ---------------------------------------------------------------------------
// GEMM: C = A @ W + bias, A[M,K] half, Wt[n][k] half (pre-transposed).
// CTA tile 128x128, 4 warps x (64x64) warp tiles — halves LDSM traffic/FLOP.
// K staged 64 at a time, 2-stage cp.async, ldmatrix frags, fp16 m16n8k16.
// Dynamic smem: 2 stages x (A 128x72 + B 128x72) halves = 73728 B.
// ---------------------------------------------------------------------------
#define GST 9216  // halves per (matrix, stage): 128*72

template <int OUTH>
__device__ __forceinline__ void gemm_body_h(
    const __half* __restrict__ A, const __half* __restrict__ Wt,
    const float* __restrict__ bias, void* Cv, float oscale, long m0, int n0) {
  extern __shared__ __half gsm[];
  __half* As = gsm;             // [2][128*72]
  __half* Bs = gsm + 2 * GST;   // [2][128*72]

  const int tid  = threadIdx.x;
  const int lane = tid & 31;
  const int wid  = tid >> 5;   // 0..3
  const int g    = lane >> 2;
  const int tg   = lane & 3;
  const int wm   = wid & 1;    // 2 m-halves of 64
  const int wn   = wid >> 1;   // 2 n-halves of 64
  const int lrow = lane & 7;
  const int koct = ((lane >> 3) & 1) << 3;
  const int hoct = (lane >> 4) << 3;

  auto stage = [&](int k0, int buf) {
#pragma unroll
    for (int i = 0; i < 8; i++) {
      int idx = tid + i * 128;
      int r = idx >> 3, c = (idx & 7) * 8;
      cp16(&As[buf * GST + r * 72 + c], A + (m0 + r) * DM_ + k0 + c);
      cp16(&Bs[buf * GST + r * 72 + c], Wt + (long)(n0 + r) * DM_ + k0 + c);
    }
    cp_commit();
  };

  float acc[4][8][4];
#pragma unroll
  for (int mt = 0; mt < 4; mt++)
#pragma unroll
    for (int nt = 0; nt < 8; nt++)
#pragma unroll
      for (int j = 0; j < 4; j++) acc[mt][nt][j] = 0.f;

  stage(0, 0);
  stage(64, 1);

  const int NT = DM_ / 64;  // 16
  for (int kt = 0; kt < NT; kt++) {
    const int buf = kt & 1;
    cp_wait1();
    __syncthreads();
    const __half* Ab = As + buf * GST;
    const __half* Bb = Bs + buf * GST;

#pragma unroll
    for (int ksp = 0; ksp < 4; ksp++) {
      int k0 = ksp * 16;
      unsigned a[4][4];
#pragma unroll
      for (int mt = 0; mt < 4; mt++) {
        int row = wm * 64 + mt * 16 + koct + lrow;
        ldsm4(a[mt], Ab + row * 72 + k0 + hoct);
      }
      unsigned bb[4][4];
#pragma unroll
      for (int np = 0; np < 4; np++) {
        int n = wn * 64 + np * 16 + hoct + lrow;
        ldsm4(bb[np], Bb + n * 72 + k0 + koct);
      }
#pragma unroll
      for (int mt = 0; mt < 4; mt++) {
#pragma unroll
        for (int np = 0; np < 4; np++) {
          mma_f16(acc[mt][2 * np],     a[mt], bb[np]);
          mma_f16(acc[mt][2 * np + 1], a[mt], bb[np] + 2);
        }
      }
    }

    __syncthreads();
    if (kt + 2 < NT) stage((kt + 2) * 64, buf);
    else cp_commit();
  }

#pragma unroll
  for (int mt = 0; mt < 4; mt++) {
    long row = m0 + wm * 64 + mt * 16 + g;
#pragma unroll
    for (int nt = 0; nt < 8; nt++) {
      int col = n0 + wn * 64 + nt * 8 + 2 * tg;
      float2 bb = *(const float2*)(bias + col);
      float v00 = (acc[mt][nt][0] + bb.x) * oscale;
      float v01 = (acc[mt][nt][1] + bb.y) * oscale;
      float v10 = (acc[mt][nt][2] + bb.x) * oscale;
      float v11 = (acc[mt][nt][3] + bb.y) * oscale;
      if (OUTH) {
        __half* C = (__half*)Cv;
        *(__half2*)(C + row * DM_ + col)       = __floats2half2_rn(v00, v01);
        *(__half2*)(C + (row + 8) * DM_ + col) = __floats2half2_rn(v10, v11);
      } else {
        float* C = (float*)Cv;
        *(float2*)(C + row * DM_ + col)       = make_float2(v00, v01);
        *(float2*)(C + (row + 8) * DM_ + col) = make_float2(v10, v11);
      }
    }
  }
}

#define QSCALE 0.18033688011112042592f  // (1/sqrt(64)) * log2(e)
#define GEMM_SMEM (4 * GST * 2)         // 73728 B

__global__ __launch_bounds__(128) void gemm_qkv_kernel(
    const __half* __restrict__ A, const __half* __restrict__ Wqt,
    const __half* __restrict__ Wkt, const __half* __restrict__ Wvt,
    const float* __restrict__ bq, const float* __restrict__ bk,
    const float* __restrict__ bv, __half* __restrict__ Qo,
    __half* __restrict__ Ko, __half* __restrict__ Vo) {
  const __half* Wt = (blockIdx.z == 0) ? Wqt : (blockIdx.z == 1) ? Wkt : Wvt;
  const float* bias = (blockIdx.z == 0) ? bq : (blockIdx.z == 1) ? bk : bv;
  __half* C = (blockIdx.z == 0) ? Qo : (blockIdx.z == 1) ? Ko : Vo;
  float sc = (blockIdx.z == 0) ? QSCALE : 1.0f;
  gemm_body_h<1>(A, Wt, bias, C, sc, (long)blockIdx.y * 128, blockIdx.x * 128);
}

__global__ __launch_bounds__(128) void gemm_out_kernel(
    const __half* __restrict__ A, const __half* __restrict__ Wt,
    const float* __restrict__ bias, float* __restrict__ C) {
  gemm_body_h<0>(A, Wt, bias, C, 1.0f, (long)blockIdx.y * 128,
                 blockIdx.x * 128);
}

// ---------------------------------------------------------------------------
// Flash attention, fp16 mma — UNCHANGED from R6/R8 best.
// ---------------------------------------------------------------------------
__global__ __launch_bounds__(128) void flash_h_kernel(
    const __half* __restrict__ Qg, const __half* __restrict__ Kg,
    const __half* __restrict__ Vg, __half* __restrict__ Og) {
  __shared__ __half Ks[2][64 * 72];
  __shared__ __half Vs[2][64 * 72];

  const int tid  = threadIdx.x;
  const int lane = tid & 31;
  const int wid  = tid >> 5;
  const int g    = lane >> 2;
  const int tg   = lane & 3;
  const int lrow = lane & 7;
  const int koct = ((lane >> 3) & 1) << 3;
  const int hoct = (lane >> 4) << 3;
  const int bh   = blockIdx.y;
  const int b    = bh >> 4;
  const int h    = bh & 15;
  const int q0   = blockIdx.x * 64;

  const __half* Qb  = Qg + ((long)(b * S_ + q0)) * DM_ + h * HD_;
  const __half* Kb0 = Kg + ((long)b * S_) * DM_ + h * HD_;
  const __half* Vb0 = Vg + ((long)b * S_) * DM_ + h * HD_;
  __half* Ob        = Og + ((long)(b * S_ + q0)) * DM_ + h * HD_;

  auto stage = [&](int kb, int p) {
    const __half* Kb = Kb0 + (long)(kb * 64) * DM_;
    const __half* Vb = Vb0 + (long)(kb * 64) * DM_;
#pragma unroll
    for (int i = 0; i < 4; i++) {
      int idx = tid + i * 128;
      int kv = idx >> 3, c = (idx & 7) * 8;
      cp16(&Ks[p][kv * 72 + c], Kb + (long)kv * DM_ + c);
      cp16(&Vs[p][kv * 72 + c], Vb + (long)kv * DM_ + c);
    }
    cp_commit();
  };

  unsigned qa[4][4];
  {
    int qrow = wid * 16 + g;
#pragma unroll
    for (int ks = 0; ks < 4; ks++) {
      int c = ks * 16 + 2 * tg;
      qa[ks][0] = *(const unsigned*)(Qb + (long)qrow * DM_ + c);
      qa[ks][1] = *(const unsigned*)(Qb + (long)(qrow + 8) * DM_ + c);
      qa[ks][2] = *(const unsigned*)(Qb + (long)qrow * DM_ + c + 8);
      qa[ks][3] = *(const unsigned*)(Qb + (long)(qrow + 8) * DM_ + c + 8);
    }
  }

  float oacc[8][4];
#pragma unroll
  for (int nt = 0; nt < 8; nt++)
#pragma unroll
    for (int j = 0; j < 4; j++) oacc[nt][j] = 0.f;
  float m0r = -INFINITY, m1r = -INFINITY, l0 = 0.f, l1 = 0.f;

  stage(0, 0);
  stage(1, 1);

  for (int kb = 0; kb < S_ / 64; kb++) {
    const int p = kb & 1;
    cp_wait1();
    __syncthreads();

    float sacc[8][4];
#pragma unroll
    for (int nt = 0; nt < 8; nt++)
#pragma unroll
      for (int j = 0; j < 4; j++) sacc[nt][j] = 0.f;
#pragma unroll
    for (int np = 0; np < 4; np++) {
#pragma unroll
      for (int ks = 0; ks < 4; ks++) {
        unsigned bb[4];
        int n = np * 16 + hoct + lrow;
        ldsm4(bb, &Ks[p][n * 72 + ks * 16 + koct]);
        mma_f16(sacc[2 * np],     qa[ks], bb);
        mma_f16(sacc[2 * np + 1], qa[ks], bb + 2);
      }
    }

    float mx0 = -INFINITY, mx1 = -INFINITY;
#pragma unroll
    for (int nt = 0; nt < 8; nt++) {
      mx0 = fmaxf(mx0, fmaxf(sacc[nt][0], sacc[nt][1]));
      mx1 = fmaxf(mx1, fmaxf(sacc[nt][2], sacc[nt][3]));
    }
#pragma unroll
    for (int off = 1; off <= 2; off <<= 1) {
      mx0 = fmaxf(mx0, __shfl_xor_sync(0xffffffffu, mx0, off));
      mx1 = fmaxf(mx1, __shfl_xor_sync(0xffffffffu, mx1, off));
    }
    float mn0 = fmaxf(m0r, mx0), mn1 = fmaxf(m1r, mx1);
    float al0 = exp2f(m0r - mn0), al1 = exp2f(m1r - mn1);
    m0r = mn0; m1r = mn1;

    float ps0 = 0.f, ps1 = 0.f;
#pragma unroll
    for (int nt = 0; nt < 8; nt++) {
      sacc[nt][0] = exp2f(sacc[nt][0] - mn0);
      sacc[nt][1] = exp2f(sacc[nt][1] - mn0);
      sacc[nt][2] = exp2f(sacc[nt][2] - mn1);
      sacc[nt][3] = exp2f(sacc[nt][3] - mn1);
      ps0 += sacc[nt][0] + sacc[nt][1];
      ps1 += sacc[nt][2] + sacc[nt][3];
    }
#pragma unroll
    for (int off = 1; off <= 2; off <<= 1) {
      ps0 += __shfl_xor_sync(0xffffffffu, ps0, off);
      ps1 += __shfl_xor_sync(0xffffffffu, ps1, off);
    }
    l0 = l0 * al0 + ps0;
    l1 = l1 * al1 + ps1;
#pragma unroll
    for (int nt = 0; nt < 8; nt++) {
      oacc[nt][0] *= al0;
      oacc[nt][1] *= al0;
      oacc[nt][2] *= al1;
      oacc[nt][3] *= al1;
    }

    unsigned pa[4][4];
#pragma unroll
    for (int ks = 0; ks < 4; ks++) {
      pa[ks][0] = pack_h2(sacc[2 * ks][0],     sacc[2 * ks][1]);
      pa[ks][1] = pack_h2(sacc[2 * ks][2],     sacc[2 * ks][3]);
      pa[ks][2] = pack_h2(sacc[2 * ks + 1][0], sacc[2 * ks + 1][1]);
      pa[ks][3] = pack_h2(sacc[2 * ks + 1][2], sacc[2 * ks + 1][3]);
    }

#pragma unroll
    for (int ks = 0; ks < 4; ks++) {
#pragma unroll
      for (int dp = 0; dp < 4; dp++) {
        unsigned vv[4];
        int kv = ks * 16 + koct + lrow;
        int d  = dp * 16 + hoct;
        ldsm4t(vv, &Vs[p][kv * 72 + d]);
        mma_f16(oacc[2 * dp],     pa[ks], vv);
        mma_f16(oacc[2 * dp + 1], pa[ks], vv + 2);
      }
    }

    __syncthreads();
    if (kb + 2 < S_ / 64) stage(kb + 2, p);
    else cp_commit();
  }

  float inv0 = 1.f / l0, inv1 = 1.f / l1;
  int row = wid * 16 + g;
#pragma unroll
  for (int nt = 0; nt < 8; nt++) {
    int col = nt * 8 + 2 * tg;
    *(__half2*)(Ob + (long)row * DM_ + col) =
        __floats2half2_rn(oacc[nt][0] * inv0, oacc[nt][1] * inv0);
    *(__half2*)(Ob + (long)(row + 8) * DM_ + col) =
        __floats2half2_rn(oacc[nt][2] * inv1, oacc[nt][3] * inv1);
  }
}

// ---------------------------------------------------------------------------
extern "C" void kernel_launch(void* const* d_in, const int* in_sizes, int n_in,
                              void* d_out, int out_size) {
  const float* x  = (const float*)d_in[0];
  const float* Wq = (const float*)d_in[1];
  const float* bq = (const float*)d_in[2];
  const float* Wk = (const float*)d_in[3];
  const float* bk = (const float*)d_in[4];
  const float* Wv = (const float*)d_in[5];
  const float* bv = (const float*)d_in[6];
  const float* Wo = (const float*)d_in[7];
  const float* bo = (const float*)d_in[8];
  float* out = (float*)d_out;

  __half *q, *k, *v, *attn, *xh, *wqt, *wkt, *wvt, *wot;
  cudaGetSymbolAddress((void**)&q, g_q);
  cudaGetSymbolAddress((void**)&k, g_k);
  cudaGetSymbolAddress((void**)&v, g_v);
  cudaGetSymbolAddress((void**)&attn, g_attn);
  cudaGetSymbolAddress((void**)&xh, g_xh);
  cudaGetSymbolAddress((void**)&wqt, g_wqt);
  cudaGetSymbolAddress((void**)&wkt, g_wkt);
  cudaGetSymbolAddress((void**)&wvt, g_wvt);
  cudaGetSymbolAddress((void**)&wot, g_wot);

  f2h_kernel<<<512, 256>>>(x, xh, (long)MROWS * DM_ / 4);
  dim3 tgrid(DM_ / 32, DM_ / 32);
  f2hT_kernel<<<tgrid, 256>>>(Wq, wqt);
  f2hT_kernel<<<tgrid, 256>>>(Wk, wkt);
  f2hT_kernel<<<tgrid, 256>>>(Wv, wvt);
  f2hT_kernel<<<tgrid, 256>>>(Wo, wot);

  cudaFuncSetAttribute(gemm_qkv_kernel,
                       cudaFuncAttributeMaxDynamicSharedMemorySize, GEMM_SMEM);
  cudaFuncSetAttribute(gemm_out_kernel,
                       cudaFuncAttributeMaxDynamicSharedMemorySize, GEMM_SMEM);

  dim3 qkvgrid(DM_ / 128, MROWS / 128, 3);
  gemm_qkv_kernel<<<qkvgrid, 128, GEMM_SMEM>>>(xh, wqt, wkt, wvt, bq, bk, bv,
                                               q, k, v);

  flash_h_kernel<<<dim3(S_ / 64, B_ * H_), 128>>>(q, k, v, attn);

  dim3 ggrid(DM_ / 128, MROWS / 128);
  gemm_out_kernel<<<ggrid, 128, GEMM_SMEM>>>(attn, wot, bo, out);
}